// round 13
// baseline (speedup 1.0000x reference)
#include <cuda_runtime.h>
#include <cuda_bf16.h>
#include <cstdint>

// Problem constants
#define BB 8
#define CC 64
#define HH 256
#define WW 256
#define HW 65536
#define TILE 16
#define HALO 2
#define EXT 20
#define EXT2 400
#define NT 256

typedef unsigned long long ull;

// ---------------- scratch ----------------------------------------------------
__device__ float d_h[BB * CC * HW];          // conv1 output (134 MB)
__device__ float d_y[BB * CC * HW];          // post-residual activation (134 MB)
__device__ float d_ca[BB * CC];
__device__ float d_spmean[BB * HW];
__device__ float d_spmax[BB * HW];
__device__ float d_sa[BB * HW];
__device__ float d_gsum[BB * CC];
__device__ unsigned int d_gmax[BB * CC];
__device__ float d_gnsum[BB * 8];
__device__ float d_gnsq[BB * 8];

// ---------------- helpers ---------------------------------------------------
__device__ __forceinline__ float silu_f(float v) {
    return __fdividef(v, 1.f + __expf(-v));
}
__device__ __forceinline__ unsigned fenc(float f) {
    unsigned u = __float_as_uint(f);
    return (u & 0x80000000u) ? ~u : (u | 0x80000000u);
}
__device__ __forceinline__ float fdec(unsigned u) {
    return (u & 0x80000000u) ? __uint_as_float(u ^ 0x80000000u)
                             : __uint_as_float(~u);
}
__device__ __forceinline__ void fma2(ull &d, ull a, ull b) {
    asm("fma.rn.f32x2 %0, %1, %2, %0;" : "+l"(d) : "l"(a), "l"(b));
}
__device__ __forceinline__ ull splat2(float v) {
    unsigned u = __float_as_uint(v);
    ull r;
    asm("mov.b64 %0, {%1, %2};" : "=l"(r) : "r"(u), "r"(u));
    return r;
}
__device__ __forceinline__ void unpack2(ull v, float &lo, float &hi) {
    unsigned a, b;
    asm("mov.b64 {%0, %1}, %2;" : "=r"(a), "=r"(b) : "l"(v));
    lo = __uint_as_float(a);
    hi = __uint_as_float(b);
}

// 32 packed FMAs: 4 pixels (xv) x 16 co (4 ulonglong2 weight vectors)
__device__ __forceinline__ void gemm32(ull *acc, float4 xv,
                                       const ulonglong2 *wp) {
    ulonglong2 W0 = wp[0], W1 = wp[1], W2 = wp[2], W3 = wp[3];
    ull s;
    s = splat2(xv.x);
    fma2(acc[0], W0.x, s); fma2(acc[1], W0.y, s);
    fma2(acc[2], W1.x, s); fma2(acc[3], W1.y, s);
    fma2(acc[4], W2.x, s); fma2(acc[5], W2.y, s);
    fma2(acc[6], W3.x, s); fma2(acc[7], W3.y, s);
    s = splat2(xv.y);
    fma2(acc[8],  W0.x, s); fma2(acc[9],  W0.y, s);
    fma2(acc[10], W1.x, s); fma2(acc[11], W1.y, s);
    fma2(acc[12], W2.x, s); fma2(acc[13], W2.y, s);
    fma2(acc[14], W3.x, s); fma2(acc[15], W3.y, s);
    s = splat2(xv.z);
    fma2(acc[16], W0.x, s); fma2(acc[17], W0.y, s);
    fma2(acc[18], W1.x, s); fma2(acc[19], W1.y, s);
    fma2(acc[20], W2.x, s); fma2(acc[21], W2.y, s);
    fma2(acc[22], W3.x, s); fma2(acc[23], W3.y, s);
    s = splat2(xv.w);
    fma2(acc[24], W0.x, s); fma2(acc[25], W0.y, s);
    fma2(acc[26], W1.x, s); fma2(acc[27], W1.y, s);
    fma2(acc[28], W2.x, s); fma2(acc[29], W2.y, s);
    fma2(acc[30], W3.x, s); fma2(acc[31], W3.y, s);
}

// ---------------- kernel 0 + alignment nops --------------------------------
__global__ void k_init() {
    int t = threadIdx.x;
    if (t < BB * CC) { d_gsum[t] = 0.f; d_gmax[t] = 0u; }
    if (t < BB * 8)  { d_gnsum[t] = 0.f; d_gnsq[t] = 0.f; }
}
__global__ void k_nop1() {}
__global__ void k_nop2() {}

// ---------------- kernel A: conv1 GEMM, h = silu(W1 x + b1) ----------------
// grid 2048 blocks x 256 threads, 2 CTAs/SM. Block = 256 consecutive pixels.
// Thread = 4-pixel quad x 16 output channels (32 f32x2 accumulators).
#define C1_SX   0                 // x tile [64][256]      16384
#define C1_W    16384             // W1T [ci][co]           4096
#define C1_B    20480             // bias                     64
#define C1_FLOATS 20544
#define C1_BYTES (C1_FLOATS * 4)

__global__ void __launch_bounds__(256, 2)
k_conv1(const float *__restrict__ x,
        const float *__restrict__ c1w, const float *__restrict__ c1b) {
    extern __shared__ float smem[];
    float *sX   = smem + C1_SX;
    float *sW1T = smem + C1_W;
    float *sCb1 = smem + C1_B;

    const int tid = threadIdx.x;
    const int b = blockIdx.x >> 8;
    const int pbase = (blockIdx.x & 255) << 8;
    const float *xb = x + ((b << 6) << 16) + pbase;

    // stage weights (transposed) + x tile, fully coalesced
    for (int i = tid; i < 4096; i += 256) {
        int ci = i >> 6, co = i & 63;
        sW1T[i] = c1w[(co << 6) | ci];
    }
    if (tid < 64) sCb1[tid] = c1b[tid];
#pragma unroll
    for (int k = 0; k < 64; k += 4) {
        int i = (k << 8) + tid;           // 4 rows per step
        sX[i]            = xb[((k + 0) << 16) + tid];
        sX[i + 256]      = xb[((k + 1) << 16) + tid];
        sX[i + 512]      = xb[((k + 2) << 16) + tid];
        sX[i + 768]      = xb[((k + 3) << 16) + tid];
    }
    __syncthreads();

    const int quad = tid >> 2, cog = tid & 3;
    const int col0 = quad << 2;

    ull acc[32];
#pragma unroll
    for (int j = 0; j < 32; j++) acc[j] = 0ull;

#pragma unroll 4
    for (int ci = 0; ci < 64; ci++) {
        float4 xv = *(const float4 *)(sX + (ci << 8) + col0);
        gemm32(acc, xv, (const ulonglong2 *)(sW1T + (ci << 6) + (cog << 4)));
    }

    // epilogue: silu(acc + bias) -> d_h, coalesced STG.128 (4 px per store)
    float *hb = d_h + ((b << 6) << 16) + pbase;
#pragma unroll
    for (int kp = 0; kp < 8; kp++) {
        int co = (cog << 4) + 2 * kp;
        float b0 = sCb1[co], b1 = sCb1[co + 1];
        float4 v0, v1;
        float lo, hi;
        unpack2(acc[0 * 8 + kp], lo, hi);
        v0.x = silu_f(lo + b0); v1.x = silu_f(hi + b1);
        unpack2(acc[1 * 8 + kp], lo, hi);
        v0.y = silu_f(lo + b0); v1.y = silu_f(hi + b1);
        unpack2(acc[2 * 8 + kp], lo, hi);
        v0.z = silu_f(lo + b0); v1.z = silu_f(hi + b1);
        unpack2(acc[3 * 8 + kp], lo, hi);
        v0.w = silu_f(lo + b0); v1.w = silu_f(hi + b1);
        *(float4 *)(hb + (co << 16) + col0)       = v0;
        *(float4 *)(hb + ((co + 1) << 16) + col0) = v1;
    }
}

// ---------------- kernel B: dw(1/3/5) + pw GEMM + residual + reductions ----
// smem layout (floats)
#define R_WPT 0                  // pw weights [c3][o]      12288
#define R_HCI 12288              // h chunk ext tile [8][400] 3200
#define R_HC  15488              // h123 chunk [24][256]     6144
#define R_SY  21632              // y tile [256][65]        16640
#define R_DW2 38272              // 576
#define R_DW3 38848              // 1600
#define R_DW1 40448
#define R_BD1 40512
#define R_BD2 40576
#define R_BD3 40640
#define R_BPW 40704
#define R_FLOATS 40768
#define R_BYTES (R_FLOATS * 4)

__global__ void __launch_bounds__(NT, 1)
k_rest(const float *__restrict__ x,
       const float *__restrict__ d1w, const float *__restrict__ d1b,
       const float *__restrict__ d2w, const float *__restrict__ d2b,
       const float *__restrict__ d3w, const float *__restrict__ d3b,
       const float *__restrict__ pww, const float *__restrict__ pwb) {
    extern __shared__ float smem[];
    float *sWpT = smem + R_WPT;
    float *sHci = smem + R_HCI;
    float *sHC  = smem + R_HC;
    float *sY   = smem + R_SY;
    float *sDw2 = smem + R_DW2;
    float *sDw3 = smem + R_DW3;
    float *sDw1 = smem + R_DW1;
    float *sBd1 = smem + R_BD1;
    float *sBd2 = smem + R_BD2;
    float *sBd3 = smem + R_BD3;
    float *sBpw = smem + R_BPW;

    const int tid = threadIdx.x;
    const int tileX = blockIdx.x, tileY = blockIdx.y, b = blockIdx.z;
    const int x0 = tileX * TILE - HALO, y0 = tileY * TILE - HALO;
    const float *hbase = d_h + ((b << 6) << 16);

    for (int i = tid; i < 12288; i += NT) {
        int c3 = i >> 6, o = i & 63;
        sWpT[i] = pww[o * 192 + c3];
    }
    for (int i = tid; i < 576;  i += NT) sDw2[i] = d2w[i];
    for (int i = tid; i < 1600; i += NT) sDw3[i] = d3w[i];
    if (tid < 64) {
        sDw1[tid] = d1w[tid];
        sBd1[tid] = d1b[tid]; sBd2[tid] = d2b[tid];
        sBd3[tid] = d3b[tid]; sBpw[tid] = pwb[tid];
    }
    __syncthreads();

    const int quad = tid >> 2, cog = tid & 3;
    const int col0 = quad << 2;
    const int dty = tid >> 4, dtx = tid & 15;
    const int dIdx = (dty + HALO) * EXT + (dtx + HALO);

    ull acc[32];
#pragma unroll
    for (int j = 0; j < 32; j++) acc[j] = 0ull;

#pragma unroll 1
    for (int cc = 0; cc < 8; cc++) {
        const int c0 = cc << 3;
        // load h chunk ext tile from global (8 channels x EXT2)
        for (int i = tid; i < 8 * EXT2; i += NT) {
            int ii = i / EXT2;
            int p = i - ii * EXT2;
            int py = p / EXT, px = p - py * EXT;
            int gy = y0 + py, gx = x0 + px;
            float v = 0.f;
            if ((unsigned)gy < HH && (unsigned)gx < WW)
                v = hbase[((c0 + ii) << 16) + (gy << 8) + gx];
            sHci[i] = v;
        }
        __syncthreads();   // also orders prior GEMM reads of sHC before dw writes

        // dw-pass: pixel = tid, channels c0..c0+7 -> sHC
#pragma unroll
        for (int i = 0; i < 8; i++) {
            const int c = c0 + i;
            const float *hb = sHci + i * EXT2;
            float center = hb[dIdx];
            float h1v = fmaf(sDw1[c], center, sBd1[c]);

            const float *w2 = sDw2 + c * 9;
            float a2 = sBd2[c], b2 = 0.f;
            a2 = fmaf(w2[0], hb[dIdx - EXT - 1], a2);
            b2 = fmaf(w2[1], hb[dIdx - EXT    ], b2);
            a2 = fmaf(w2[2], hb[dIdx - EXT + 1], a2);
            b2 = fmaf(w2[3], hb[dIdx - 1], b2);
            a2 = fmaf(w2[4], center, a2);
            b2 = fmaf(w2[5], hb[dIdx + 1], b2);
            a2 = fmaf(w2[6], hb[dIdx + EXT - 1], a2);
            b2 = fmaf(w2[7], hb[dIdx + EXT    ], b2);
            a2 = fmaf(w2[8], hb[dIdx + EXT + 1], a2);
            float h2v = a2 + b2;

            const float *w3 = sDw3 + c * 25;
            float a3 = sBd3[c], b3 = 0.f, c3v = 0.f;
#pragma unroll
            for (int dy = -2; dy <= 2; dy++) {
                int rb = (dy + 2) * 5;
                int hbIdx = dIdx + dy * EXT;
                a3  = fmaf(w3[rb + 0], hb[hbIdx - 2], a3);
                b3  = fmaf(w3[rb + 1], hb[hbIdx - 1], b3);
                c3v = fmaf(w3[rb + 2], hb[hbIdx    ], c3v);
                a3  = fmaf(w3[rb + 3], hb[hbIdx + 1], a3);
                b3  = fmaf(w3[rb + 4], hb[hbIdx + 2], b3);
            }
            float h3v = (a3 + b3) + c3v;

            sHC[(0 * 8 + i) * 256 + tid] = h1v;
            sHC[(1 * 8 + i) * 256 + tid] = h2v;
            sHC[(2 * 8 + i) * 256 + tid] = h3v;
        }
        __syncthreads();

        // GEMM accumulate over the 24 k-rows of this chunk
#pragma unroll
        for (int t = 0; t < 3; t++)
#pragma unroll
            for (int i = 0; i < 8; i++) {
                const int krow = t * 64 + c0 + i;
                float4 hv = *(const float4 *)(sHC + (t * 8 + i) * 256 + col0);
                gemm32(acc, hv,
                       (const ulonglong2 *)(sWpT + (krow << 6) + (cog << 4)));
            }
        __syncthreads();
    }

    // epilogue: t = silu(pw + bias) -> sY
#pragma unroll
    for (int j = 0; j < 4; j++) {
        int px = col0 + j;
#pragma unroll
        for (int kp = 0; kp < 8; kp++) {
            float lo, hi;
            unpack2(acc[j * 8 + kp], lo, hi);
            int co = (cog << 4) + 2 * kp;
            sY[px * 65 + co]     = silu_f(lo + sBpw[co]);
            sY[px * 65 + co + 1] = silu_f(hi + sBpw[co + 1]);
        }
    }
    __syncthreads();

    // residual + second silu, write d_y (coalesced per channel)
    {
        const int gy = tileY * TILE + dty, gx = tileX * TILE + dtx;
        const int gpix = (gy << 8) | gx;
        const float *xr = x + ((b << 6) << 16) + gpix;
        float *yb = d_y + ((b << 6) << 16) + gpix;
#pragma unroll 8
        for (int c = 0; c < 64; c++) {
            float t = sY[tid * 65 + c];
            float yv = silu_f(t + xr[c << 16]);
            yb[c << 16] = yv;
            sY[tid * 65 + c] = yv;
        }
    }
    __syncthreads();

    // per-(b,c) reduction for channel attention
    if (tid < 64) {
        float s = 0.f, m = -3e38f;
#pragma unroll 4
        for (int p = 0; p < 256; p++) {
            float v = sY[p * 65 + tid];
            s += v;
            m = fmaxf(m, v);
        }
        atomicAdd(&d_gsum[(b << 6) | tid], s);
        atomicMax(&d_gmax[(b << 6) | tid], fenc(m));
    }
}

// ---------------- kernel 2: channel attention MLP --------------------------
__global__ void k_ca(const float *__restrict__ caw1, const float *__restrict__ caw2) {
    int b = blockIdx.x, c = threadIdx.x;
    __shared__ float pa[64], pm[64], ha[8], hm[8];
    pa[c] = d_gsum[(b << 6) | c] * (1.f / 65536.f);
    pm[c] = fdec(d_gmax[(b << 6) | c]);
    __syncthreads();
    if (c < 8) {
        float sa_ = 0.f, sm_ = 0.f;
#pragma unroll
        for (int i = 0; i < 64; i++) {
            float w = caw1[c * 64 + i];
            sa_ += w * pa[i];
            sm_ += w * pm[i];
        }
        ha[c] = fmaxf(sa_, 0.f);
        hm[c] = fmaxf(sm_, 0.f);
    }
    __syncthreads();
    float oa = 0.f, om = 0.f;
#pragma unroll
    for (int j = 0; j < 8; j++) {
        float w = caw2[c * 8 + j];
        oa += w * ha[j];
        om += w * hm[j];
    }
    d_ca[(b << 6) | c] = silu_f(oa + om);
}

// ---------------- kernel 3: spatial mean/max over channels -----------------
__global__ void k_sp() {
    int b = blockIdx.x >> 8;
    int y = blockIdx.x & 255;
    int xx = threadIdx.x;
    int p = (y << 8) | xx;
    const float *yb = d_y + ((b << 6) << 16) + p;
    const float *cab = d_ca + (b << 6);
    float s = 0.f, m = -3e38f;
#pragma unroll 8
    for (int c = 0; c < 64; c++) {
        float v = cab[c] * yb[c << 16];
        s += v;
        m = fmaxf(m, v);
    }
    d_spmean[(b << 16) | p] = s * (1.f / 64.f);
    d_spmax[(b << 16) | p] = m;
}

// ---------------- kernel 4: spatial attention 7x7 conv ---------------------
__global__ void k_sa(const float *__restrict__ saw, const float *__restrict__ sab) {
    __shared__ float sm[2][22][22];
    __shared__ float sw[98];
    int tx = threadIdx.x, ty = threadIdx.y;
    int tid = ty * 16 + tx;
    int b = blockIdx.z;
    int gx0 = blockIdx.x * 16 - 3, gy0 = blockIdx.y * 16 - 3;
    if (tid < 98) sw[tid] = saw[tid];
    for (int i = tid; i < 2 * 22 * 22; i += 256) {
        int ch = i / 484;
        int r = i - ch * 484;
        int py = r / 22, px = r - py * 22;
        int gy = gy0 + py, gx = gx0 + px;
        float v = 0.f;
        if ((unsigned)gy < HH && (unsigned)gx < WW)
            v = (ch ? d_spmax : d_spmean)[(b << 16) + (gy << 8) + gx];
        sm[ch][py][px] = v;
    }
    __syncthreads();
    float acc = sab[0];
#pragma unroll
    for (int ch = 0; ch < 2; ch++)
#pragma unroll
        for (int dy = 0; dy < 7; dy++)
#pragma unroll
            for (int dx = 0; dx < 7; dx++)
                acc = fmaf(sw[ch * 49 + dy * 7 + dx], sm[ch][ty + dy][tx + dx], acc);
    int gy = blockIdx.y * 16 + ty, gx = blockIdx.x * 16 + tx;
    d_sa[(b << 16) + (gy << 8) + gx] = silu_f(acc);
}

// ---------------- kernel 5: groupnorm statistics ---------------------------
__global__ void k_gnstats() {
    int chunk = blockIdx.x, c = blockIdx.y, b = blockIdx.z;
    int tid = threadIdx.x;
    float cav = d_ca[(b << 6) | c];
    const float *yb = d_y + (((b << 6) | c) << 16);
    const float *sab = d_sa + (b << 16);
    int base = chunk * 4096;
    float s = 0.f, sq = 0.f;
#pragma unroll
    for (int i = 0; i < 16; i++) {
        int p = base + (i << 8) + tid;
        float v = sab[p] * cav * yb[p];
        s += v;
        sq += v * v;
    }
#pragma unroll
    for (int o = 16; o; o >>= 1) {
        s  += __shfl_xor_sync(0xFFFFFFFFu, s, o);
        sq += __shfl_xor_sync(0xFFFFFFFFu, sq, o);
    }
    __shared__ float ws[8], wq[8];
    int w = tid >> 5, l = tid & 31;
    if (!l) { ws[w] = s; wq[w] = sq; }
    __syncthreads();
    if (tid == 0) {
        float S = 0.f, Q = 0.f;
#pragma unroll
        for (int i = 0; i < 8; i++) { S += ws[i]; Q += wq[i]; }
        atomicAdd(&d_gnsum[(b << 3) | (c >> 3)], S);
        atomicAdd(&d_gnsq[(b << 3) | (c >> 3)], Q);
    }
}

// ---------------- kernel 6: groupnorm apply + silu -> out ------------------
__global__ void k_fin(float *__restrict__ out,
                      const float *__restrict__ gng, const float *__restrict__ gnb) {
    int chunk = blockIdx.x, c = blockIdx.y, b = blockIdx.z;
    int tid = threadIdx.x;
    float cav = d_ca[(b << 6) | c];
    int gi = (b << 3) | (c >> 3);
    const float Ninv = 1.f / 524288.f;
    float mu = d_gnsum[gi] * Ninv;
    float var = d_gnsq[gi] * Ninv - mu * mu;
    float inv = rsqrtf(var + 1e-5f);
    float ga = gng[c], be = gnb[c];
    int coff = ((b << 6) | c) << 16;
    const float *yb = d_y + coff;
    const float *sab = d_sa + (b << 16);
    float *ob = out + coff;
    int base = chunk * 4096;
#pragma unroll
    for (int i = 0; i < 16; i++) {
        int p = base + (i << 8) + tid;
        float v = sab[p] * cav * yb[p];
        float g = (v - mu) * inv * ga + be;
        ob[p] = silu_f(g);
    }
}

// ---------------- launch ----------------------------------------------------
extern "C" void kernel_launch(void *const *d_in, const int *in_sizes, int n_in,
                              void *d_out, int out_size) {
    const float *x      = (const float *)d_in[0];
    const float *c1w    = (const float *)d_in[1];
    const float *c1b    = (const float *)d_in[2];
    const float *d1w    = (const float *)d_in[3];
    const float *d1b    = (const float *)d_in[4];
    const float *d2w    = (const float *)d_in[5];
    const float *d2b    = (const float *)d_in[6];
    const float *d3w    = (const float *)d_in[7];
    const float *d3b    = (const float *)d_in[8];
    const float *pww    = (const float *)d_in[9];
    const float *pwb    = (const float *)d_in[10];
    const float *caw1   = (const float *)d_in[11];
    const float *caw2   = (const float *)d_in[12];
    const float *saw    = (const float *)d_in[13];
    const float *sab    = (const float *)d_in[14];
    const float *gng    = (const float *)d_in[15];
    const float *gnb    = (const float *)d_in[16];

    cudaFuncSetAttribute(k_conv1, cudaFuncAttributeMaxDynamicSharedMemorySize,
                         C1_BYTES);
    cudaFuncSetAttribute(k_rest, cudaFuncAttributeMaxDynamicSharedMemorySize,
                         R_BYTES);

    k_init<<<1, 512>>>();
    k_nop1<<<1, 32>>>();
    k_nop2<<<1, 32>>>();
    // launch #4 -> profiled by ncu (-s 5 -c 1 empirically captures the 4th launch)
    k_conv1<<<2048, 256, C1_BYTES>>>(x, c1w, c1b);
    k_rest<<<dim3(16, 16, 8), NT, R_BYTES>>>(
        x, d1w, d1b, d2w, d2b, d3w, d3b, pww, pwb);
    k_ca<<<8, 64>>>(caw1, caw2);
    k_sp<<<BB * HH, 256>>>();
    k_sa<<<dim3(16, 16, 8), dim3(16, 16)>>>(saw, sab);
    k_gnstats<<<dim3(16, 64, 8), 256>>>();
    k_fin<<<dim3(16, 64, 8), 256>>>((float *)d_out, gng, gnb);
}

// round 16
// speedup vs baseline: 1.7568x; 1.7568x over previous
#include <cuda_runtime.h>
#include <cuda_bf16.h>
#include <cstdint>

// Problem constants
#define BB 8
#define CC 64
#define HH 256
#define WW 256
#define HW 65536
#define TILE 16
#define HALO 2
#define EXT 20
#define EXT2 400
#define NT 256

typedef unsigned long long ull;

// ---------------- weights in constant memory (64KB exactly) ------------------
__constant__ float cW1T[64 * 64];      // conv1 [ci][co]
__constant__ float cWpT[192 * 64];     // pw    [c3][o]

// ---------------- scratch ----------------------------------------------------
__device__ float d_w1Ts[64 * 64];      // transpose staging
__device__ float d_wpTs[192 * 64];
__device__ float d_h[BB * CC * HW];
__device__ float d_y[BB * CC * HW];
__device__ float d_ca[BB * CC];
__device__ float d_spmean[BB * HW];
__device__ float d_spmax[BB * HW];
__device__ float d_sa[BB * HW];
__device__ float d_gsum[BB * CC];
__device__ unsigned int d_gmax[BB * CC];
__device__ float d_gnsum[BB * 8];
__device__ float d_gnsq[BB * 8];

// ---------------- helpers ---------------------------------------------------
__device__ __forceinline__ float silu_f(float v) {
    return __fdividef(v, 1.f + __expf(-v));
}
__device__ __forceinline__ unsigned fenc(float f) {
    unsigned u = __float_as_uint(f);
    return (u & 0x80000000u) ? ~u : (u | 0x80000000u);
}
__device__ __forceinline__ float fdec(unsigned u) {
    return (u & 0x80000000u) ? __uint_as_float(u ^ 0x80000000u)
                             : __uint_as_float(~u);
}
__device__ __forceinline__ void fma2(ull &d, ull a, ull b) {
    asm("fma.rn.f32x2 %0, %1, %2, %0;" : "+l"(d) : "l"(a), "l"(b));
}
__device__ __forceinline__ ull splat2(float v) {
    unsigned u = __float_as_uint(v);
    ull r;
    asm("mov.b64 %0, {%1, %2};" : "=l"(r) : "r"(u), "r"(u));
    return r;
}
__device__ __forceinline__ void unpack2(ull v, float &lo, float &hi) {
    unsigned a, b;
    asm("mov.b64 {%0, %1}, %2;" : "=r"(a), "=r"(b) : "l"(v));
    lo = __uint_as_float(a);
    hi = __uint_as_float(b);
}

// 32 packed FMAs: 4 pixels (xv) x 16 co, weights from __constant__ (plain
// C++ deref -> compiler emits ld.const.v2.u64; warp-uniform addr -> broadcast)
__device__ __forceinline__ void gemm32c(ull *acc, float4 xv, const float *wbase) {
    ulonglong2 W0 = *(const ulonglong2 *)(wbase);
    ulonglong2 W1 = *(const ulonglong2 *)(wbase + 4);
    ulonglong2 W2 = *(const ulonglong2 *)(wbase + 8);
    ulonglong2 W3 = *(const ulonglong2 *)(wbase + 12);
    ull s;
    s = splat2(xv.x);
    fma2(acc[0], W0.x, s); fma2(acc[1], W0.y, s);
    fma2(acc[2], W1.x, s); fma2(acc[3], W1.y, s);
    fma2(acc[4], W2.x, s); fma2(acc[5], W2.y, s);
    fma2(acc[6], W3.x, s); fma2(acc[7], W3.y, s);
    s = splat2(xv.y);
    fma2(acc[8],  W0.x, s); fma2(acc[9],  W0.y, s);
    fma2(acc[10], W1.x, s); fma2(acc[11], W1.y, s);
    fma2(acc[12], W2.x, s); fma2(acc[13], W2.y, s);
    fma2(acc[14], W3.x, s); fma2(acc[15], W3.y, s);
    s = splat2(xv.z);
    fma2(acc[16], W0.x, s); fma2(acc[17], W0.y, s);
    fma2(acc[18], W1.x, s); fma2(acc[19], W1.y, s);
    fma2(acc[20], W2.x, s); fma2(acc[21], W2.y, s);
    fma2(acc[22], W3.x, s); fma2(acc[23], W3.y, s);
    s = splat2(xv.w);
    fma2(acc[24], W0.x, s); fma2(acc[25], W0.y, s);
    fma2(acc[26], W1.x, s); fma2(acc[27], W1.y, s);
    fma2(acc[28], W2.x, s); fma2(acc[29], W2.y, s);
    fma2(acc[30], W3.x, s); fma2(acc[31], W3.y, s);
}

// ---------------- kernel 0: init + weight transpose ------------------------
__global__ void k_init() {
    int t = threadIdx.x;
    if (t < BB * CC) { d_gsum[t] = 0.f; d_gmax[t] = 0u; }
    if (t < BB * 8)  { d_gnsum[t] = 0.f; d_gnsq[t] = 0.f; }
}
__global__ void k_prep(const float *__restrict__ c1w, const float *__restrict__ pww) {
    int t = blockIdx.x * 256 + threadIdx.x;
    if (t < 4096) {
        int ci = t >> 6, co = t & 63;
        d_w1Ts[t] = c1w[(co << 6) | ci];
    }
    if (t < 12288) {
        int c3 = t >> 6, o = t & 63;
        d_wpTs[t] = pww[o * 192 + c3];
    }
}

// ---------------- kernel A: conv1 GEMM, h = silu(W1 x + b1) ----------------
// Warp w: cog = w&3 (16 co, warp-uniform -> LDC broadcast);
// pixel quad = (w>>2)*32 + lane.
#define C1_SX   0
#define C1_B    16384
#define C1_FLOATS 16448
#define C1_BYTES (C1_FLOATS * 4)

__global__ void __launch_bounds__(256, 2)
k_conv1(const float *__restrict__ x, const float *__restrict__ c1b) {
    extern __shared__ float smem[];
    float *sX   = smem + C1_SX;
    float *sCb1 = smem + C1_B;

    const int tid = threadIdx.x;
    const int b = blockIdx.x >> 8;
    const int pbase = (blockIdx.x & 255) << 8;
    const float *xb = x + ((b << 6) << 16) + pbase;

    if (tid < 64) sCb1[tid] = c1b[tid];
#pragma unroll
    for (int k = 0; k < 64; k += 4) {
        int i = (k << 8) + tid;
        sX[i]       = xb[((k + 0) << 16) + tid];
        sX[i + 256] = xb[((k + 1) << 16) + tid];
        sX[i + 512] = xb[((k + 2) << 16) + tid];
        sX[i + 768] = xb[((k + 3) << 16) + tid];
    }
    __syncthreads();

    const int wid = tid >> 5, lane = tid & 31;
    const int cog = wid & 3;                     // warp-uniform
    const int quad = ((wid >> 2) << 5) + lane;   // 0..63
    const int col0 = quad << 2;

    ull acc[32];
#pragma unroll
    for (int j = 0; j < 32; j++) acc[j] = 0ull;

#pragma unroll 4
    for (int ci = 0; ci < 64; ci++) {
        float4 xv = *(const float4 *)(sX + (ci << 8) + col0);
        gemm32c(acc, xv, cW1T + (ci << 6) + (cog << 4));
    }

    float *hb = d_h + ((b << 6) << 16) + pbase;
#pragma unroll
    for (int kp = 0; kp < 8; kp++) {
        int co = (cog << 4) + 2 * kp;
        float b0 = sCb1[co], b1 = sCb1[co + 1];
        float4 v0, v1;
        float lo, hi;
        unpack2(acc[0 * 8 + kp], lo, hi);
        v0.x = silu_f(lo + b0); v1.x = silu_f(hi + b1);
        unpack2(acc[1 * 8 + kp], lo, hi);
        v0.y = silu_f(lo + b0); v1.y = silu_f(hi + b1);
        unpack2(acc[2 * 8 + kp], lo, hi);
        v0.z = silu_f(lo + b0); v1.z = silu_f(hi + b1);
        unpack2(acc[3 * 8 + kp], lo, hi);
        v0.w = silu_f(lo + b0); v1.w = silu_f(hi + b1);
        *(float4 *)(hb + (co << 16) + col0)       = v0;
        *(float4 *)(hb + ((co + 1) << 16) + col0) = v1;
    }
}

// ---------------- kernel B: dw(1/3/5) + pw GEMM + residual + reductions ----
#define R_HCI 0                  // h chunk ext tile [8][400]  3200
#define R_HC  3200               // h123 chunk [24][256]       6144
#define R_DW2 9344               // 576
#define R_DW3 9920               // 1600
#define R_DW1 11520
#define R_BD1 11584
#define R_BD2 11648
#define R_BD3 11712
#define R_BPW 11776
#define R_SUM 11840              // [8][16]
#define R_MAX 11968              // [8][16]
#define R_FLOATS 12096
#define R_BYTES (R_FLOATS * 4)

__global__ void __launch_bounds__(NT, 2)
k_rest(const float *__restrict__ x,
       const float *__restrict__ d1w, const float *__restrict__ d1b,
       const float *__restrict__ d2w, const float *__restrict__ d2b,
       const float *__restrict__ d3w, const float *__restrict__ d3b,
       const float *__restrict__ pwb) {
    extern __shared__ float smem[];
    float *sHci = smem + R_HCI;
    float *sHC  = smem + R_HC;
    float *sDw2 = smem + R_DW2;
    float *sDw3 = smem + R_DW3;
    float *sDw1 = smem + R_DW1;
    float *sBd1 = smem + R_BD1;
    float *sBd2 = smem + R_BD2;
    float *sBd3 = smem + R_BD3;
    float *sBpw = smem + R_BPW;
    float *sSum = smem + R_SUM;
    float *sMax = smem + R_MAX;

    const int tid = threadIdx.x;
    const int tileX = blockIdx.x, tileY = blockIdx.y, b = blockIdx.z;
    const int x0 = tileX * TILE - HALO, y0 = tileY * TILE - HALO;
    const float *hbase = d_h + ((b << 6) << 16);

    for (int i = tid; i < 576;  i += NT) sDw2[i] = d2w[i];
    for (int i = tid; i < 1600; i += NT) sDw3[i] = d3w[i];
    if (tid < 64) {
        sDw1[tid] = d1w[tid];
        sBd1[tid] = d1b[tid]; sBd2[tid] = d2b[tid];
        sBd3[tid] = d3b[tid]; sBpw[tid] = pwb[tid];
    }
    __syncthreads();

    const int wid = tid >> 5, lane = tid & 31;
    const int cog = wid & 3;                     // warp-uniform
    const int quad = ((wid >> 2) << 5) + lane;   // 0..63
    const int col0 = quad << 2;
    const int dty = tid >> 4, dtx = tid & 15;
    const int dIdx = (dty + HALO) * EXT + (dtx + HALO);

    ull acc[32];
#pragma unroll
    for (int j = 0; j < 32; j++) acc[j] = 0ull;

#pragma unroll 1
    for (int cc = 0; cc < 8; cc++) {
        const int c0 = cc << 3;
        for (int i = tid; i < 8 * EXT2; i += NT) {
            int ii = i / EXT2;
            int p = i - ii * EXT2;
            int py = p / EXT, px = p - py * EXT;
            int gy = y0 + py, gx = x0 + px;
            float v = 0.f;
            if ((unsigned)gy < HH && (unsigned)gx < WW)
                v = hbase[((c0 + ii) << 16) + (gy << 8) + gx];
            sHci[i] = v;
        }
        __syncthreads();

#pragma unroll
        for (int i = 0; i < 8; i++) {
            const int c = c0 + i;
            const float *hb = sHci + i * EXT2;
            float center = hb[dIdx];
            float h1v = fmaf(sDw1[c], center, sBd1[c]);

            const float *w2 = sDw2 + c * 9;
            float a2 = sBd2[c], b2 = 0.f;
            a2 = fmaf(w2[0], hb[dIdx - EXT - 1], a2);
            b2 = fmaf(w2[1], hb[dIdx - EXT    ], b2);
            a2 = fmaf(w2[2], hb[dIdx - EXT + 1], a2);
            b2 = fmaf(w2[3], hb[dIdx - 1], b2);
            a2 = fmaf(w2[4], center, a2);
            b2 = fmaf(w2[5], hb[dIdx + 1], b2);
            a2 = fmaf(w2[6], hb[dIdx + EXT - 1], a2);
            b2 = fmaf(w2[7], hb[dIdx + EXT    ], b2);
            a2 = fmaf(w2[8], hb[dIdx + EXT + 1], a2);
            float h2v = a2 + b2;

            const float *w3 = sDw3 + c * 25;
            float a3 = sBd3[c], b3 = 0.f, c3v = 0.f;
#pragma unroll
            for (int dy = -2; dy <= 2; dy++) {
                int rb = (dy + 2) * 5;
                int hbIdx = dIdx + dy * EXT;
                a3  = fmaf(w3[rb + 0], hb[hbIdx - 2], a3);
                b3  = fmaf(w3[rb + 1], hb[hbIdx - 1], b3);
                c3v = fmaf(w3[rb + 2], hb[hbIdx    ], c3v);
                a3  = fmaf(w3[rb + 3], hb[hbIdx + 1], a3);
                b3  = fmaf(w3[rb + 4], hb[hbIdx + 2], b3);
            }
            float h3v = (a3 + b3) + c3v;

            sHC[(0 * 8 + i) * 256 + tid] = h1v;
            sHC[(1 * 8 + i) * 256 + tid] = h2v;
            sHC[(2 * 8 + i) * 256 + tid] = h3v;
        }
        __syncthreads();

#pragma unroll
        for (int t = 0; t < 3; t++)
#pragma unroll
            for (int i = 0; i < 8; i++) {
                const int krow = t * 64 + c0 + i;
                float4 hv = *(const float4 *)(sHC + (t * 8 + i) * 256 + col0);
                gemm32c(acc, hv, cWpT + (krow << 6) + (cog << 4));
            }
        __syncthreads();
    }

    // epilogue: silu(pw+bias) + residual + silu -> d_y, then warp reductions
    const int prow = col0 >> 4, pcol = col0 & 15;
    const int gpix0 = ((tileY * TILE + prow) << 8) + tileX * TILE + pcol;
    const float *xq = x + ((b << 6) << 16) + gpix0;
    float *yq = d_y + ((b << 6) << 16) + gpix0;

#pragma unroll
    for (int kp = 0; kp < 8; kp++) {
        int co0 = (cog << 4) + 2 * kp, co1 = co0 + 1;
        float bp0 = sBpw[co0], bp1 = sBpw[co1];
        float4 xv0 = *(const float4 *)(xq + (co0 << 16));
        float4 xv1 = *(const float4 *)(xq + (co1 << 16));
        float4 y0, y1;
        float lo, hi;
        unpack2(acc[0 * 8 + kp], lo, hi);
        y0.x = silu_f(silu_f(lo + bp0) + xv0.x);
        y1.x = silu_f(silu_f(hi + bp1) + xv1.x);
        unpack2(acc[1 * 8 + kp], lo, hi);
        y0.y = silu_f(silu_f(lo + bp0) + xv0.y);
        y1.y = silu_f(silu_f(hi + bp1) + xv1.y);
        unpack2(acc[2 * 8 + kp], lo, hi);
        y0.z = silu_f(silu_f(lo + bp0) + xv0.z);
        y1.z = silu_f(silu_f(hi + bp1) + xv1.z);
        unpack2(acc[3 * 8 + kp], lo, hi);
        y0.w = silu_f(silu_f(lo + bp0) + xv0.w);
        y1.w = silu_f(silu_f(hi + bp1) + xv1.w);
        *(float4 *)(yq + (co0 << 16)) = y0;
        *(float4 *)(yq + (co1 << 16)) = y1;

        float s0 = (y0.x + y0.y) + (y0.z + y0.w);
        float s1 = (y1.x + y1.y) + (y1.z + y1.w);
        float m0 = fmaxf(fmaxf(y0.x, y0.y), fmaxf(y0.z, y0.w));
        float m1 = fmaxf(fmaxf(y1.x, y1.y), fmaxf(y1.z, y1.w));
#pragma unroll
        for (int o = 16; o; o >>= 1) {
            s0 += __shfl_xor_sync(0xFFFFFFFFu, s0, o);
            s1 += __shfl_xor_sync(0xFFFFFFFFu, s1, o);
            m0 = fmaxf(m0, __shfl_xor_sync(0xFFFFFFFFu, m0, o));
            m1 = fmaxf(m1, __shfl_xor_sync(0xFFFFFFFFu, m1, o));
        }
        if (lane == 0) {
            sSum[wid * 16 + 2 * kp]     = s0;
            sSum[wid * 16 + 2 * kp + 1] = s1;
            sMax[wid * 16 + 2 * kp]     = m0;
            sMax[wid * 16 + 2 * kp + 1] = m1;
        }
    }
    __syncthreads();

    if (tid < 64) {
        int cg = tid >> 4, k = tid & 15;
        float s = sSum[cg * 16 + k] + sSum[(cg + 4) * 16 + k];
        float m = fmaxf(sMax[cg * 16 + k], sMax[(cg + 4) * 16 + k]);
        atomicAdd(&d_gsum[(b << 6) | tid], s);
        atomicMax(&d_gmax[(b << 6) | tid], fenc(m));
    }
}

// ---------------- kernel 2: channel attention MLP --------------------------
__global__ void k_ca(const float *__restrict__ caw1, const float *__restrict__ caw2) {
    int b = blockIdx.x, c = threadIdx.x;
    __shared__ float pa[64], pm[64], ha[8], hm[8];
    pa[c] = d_gsum[(b << 6) | c] * (1.f / 65536.f);
    pm[c] = fdec(d_gmax[(b << 6) | c]);
    __syncthreads();
    if (c < 8) {
        float sa_ = 0.f, sm_ = 0.f;
#pragma unroll
        for (int i = 0; i < 64; i++) {
            float w = caw1[c * 64 + i];
            sa_ += w * pa[i];
            sm_ += w * pm[i];
        }
        ha[c] = fmaxf(sa_, 0.f);
        hm[c] = fmaxf(sm_, 0.f);
    }
    __syncthreads();
    float oa = 0.f, om = 0.f;
#pragma unroll
    for (int j = 0; j < 8; j++) {
        float w = caw2[c * 8 + j];
        oa += w * ha[j];
        om += w * hm[j];
    }
    d_ca[(b << 6) | c] = silu_f(oa + om);
}

// ---------------- kernel 3: spatial mean/max over channels -----------------
__global__ void k_sp() {
    int b = blockIdx.x >> 8;
    int y = blockIdx.x & 255;
    int xx = threadIdx.x;
    int p = (y << 8) | xx;
    const float *yb = d_y + ((b << 6) << 16) + p;
    const float *cab = d_ca + (b << 6);
    float s = 0.f, m = -3e38f;
#pragma unroll 8
    for (int c = 0; c < 64; c++) {
        float v = cab[c] * yb[c << 16];
        s += v;
        m = fmaxf(m, v);
    }
    d_spmean[(b << 16) | p] = s * (1.f / 64.f);
    d_spmax[(b << 16) | p] = m;
}

// ---------------- kernel 4: spatial attention 7x7 conv ---------------------
__global__ void k_sa(const float *__restrict__ saw, const float *__restrict__ sab) {
    __shared__ float sm[2][22][22];
    __shared__ float sw[98];
    int tx = threadIdx.x, ty = threadIdx.y;
    int tid = ty * 16 + tx;
    int b = blockIdx.z;
    int gx0 = blockIdx.x * 16 - 3, gy0 = blockIdx.y * 16 - 3;
    if (tid < 98) sw[tid] = saw[tid];
    for (int i = tid; i < 2 * 22 * 22; i += 256) {
        int ch = i / 484;
        int r = i - ch * 484;
        int py = r / 22, px = r - py * 22;
        int gy = gy0 + py, gx = gx0 + px;
        float v = 0.f;
        if ((unsigned)gy < HH && (unsigned)gx < WW)
            v = (ch ? d_spmax : d_spmean)[(b << 16) + (gy << 8) + gx];
        sm[ch][py][px] = v;
    }
    __syncthreads();
    float acc = sab[0];
#pragma unroll
    for (int ch = 0; ch < 2; ch++)
#pragma unroll
        for (int dy = 0; dy < 7; dy++)
#pragma unroll
            for (int dx = 0; dx < 7; dx++)
                acc = fmaf(sw[ch * 49 + dy * 7 + dx], sm[ch][ty + dy][tx + dx], acc);
    int gy = blockIdx.y * 16 + ty, gx = blockIdx.x * 16 + tx;
    d_sa[(b << 16) + (gy << 8) + gx] = silu_f(acc);
}

// ---------------- kernel 5: groupnorm statistics ---------------------------
__global__ void k_gnstats() {
    int chunk = blockIdx.x, c = blockIdx.y, b = blockIdx.z;
    int tid = threadIdx.x;
    float cav = d_ca[(b << 6) | c];
    const float *yb = d_y + (((b << 6) | c) << 16);
    const float *sab = d_sa + (b << 16);
    int base = chunk * 4096;
    float s = 0.f, sq = 0.f;
#pragma unroll
    for (int i = 0; i < 16; i++) {
        int p = base + (i << 8) + tid;
        float v = sab[p] * cav * yb[p];
        s += v;
        sq += v * v;
    }
#pragma unroll
    for (int o = 16; o; o >>= 1) {
        s  += __shfl_xor_sync(0xFFFFFFFFu, s, o);
        sq += __shfl_xor_sync(0xFFFFFFFFu, sq, o);
    }
    __shared__ float ws[8], wq[8];
    int w = tid >> 5, l = tid & 31;
    if (!l) { ws[w] = s; wq[w] = sq; }
    __syncthreads();
    if (tid == 0) {
        float S = 0.f, Q = 0.f;
#pragma unroll
        for (int i = 0; i < 8; i++) { S += ws[i]; Q += wq[i]; }
        atomicAdd(&d_gnsum[(b << 3) | (c >> 3)], S);
        atomicAdd(&d_gnsq[(b << 3) | (c >> 3)], Q);
    }
}

// ---------------- kernel 6: groupnorm apply + silu -> out ------------------
__global__ void k_fin(float *__restrict__ out,
                      const float *__restrict__ gng, const float *__restrict__ gnb) {
    int chunk = blockIdx.x, c = blockIdx.y, b = blockIdx.z;
    int tid = threadIdx.x;
    float cav = d_ca[(b << 6) | c];
    int gi = (b << 3) | (c >> 3);
    const float Ninv = 1.f / 524288.f;
    float mu = d_gnsum[gi] * Ninv;
    float var = d_gnsq[gi] * Ninv - mu * mu;
    float inv = rsqrtf(var + 1e-5f);
    float ga = gng[c], be = gnb[c];
    int coff = ((b << 6) | c) << 16;
    const float *yb = d_y + coff;
    const float *sab = d_sa + (b << 16);
    float *ob = out + coff;
    int base = chunk * 4096;
#pragma unroll
    for (int i = 0; i < 16; i++) {
        int p = base + (i << 8) + tid;
        float v = sab[p] * cav * yb[p];
        float g = (v - mu) * inv * ga + be;
        ob[p] = silu_f(g);
    }
}

// ---------------- launch ----------------------------------------------------
extern "C" void kernel_launch(void *const *d_in, const int *in_sizes, int n_in,
                              void *d_out, int out_size) {
    const float *x      = (const float *)d_in[0];
    const float *c1w    = (const float *)d_in[1];
    const float *c1b    = (const float *)d_in[2];
    const float *d1w    = (const float *)d_in[3];
    const float *d1b    = (const float *)d_in[4];
    const float *d2w    = (const float *)d_in[5];
    const float *d2b    = (const float *)d_in[6];
    const float *d3w    = (const float *)d_in[7];
    const float *d3b    = (const float *)d_in[8];
    const float *pww    = (const float *)d_in[9];
    const float *pwb    = (const float *)d_in[10];
    const float *caw1   = (const float *)d_in[11];
    const float *caw2   = (const float *)d_in[12];
    const float *saw    = (const float *)d_in[13];
    const float *sab    = (const float *)d_in[14];
    const float *gng    = (const float *)d_in[15];
    const float *gnb    = (const float *)d_in[16];

    cudaFuncSetAttribute(k_conv1, cudaFuncAttributeMaxDynamicSharedMemorySize,
                         C1_BYTES);
    cudaFuncSetAttribute(k_rest, cudaFuncAttributeMaxDynamicSharedMemorySize,
                         R_BYTES);

    void *w1s = nullptr, *wps = nullptr;
    cudaGetSymbolAddress(&w1s, d_w1Ts);
    cudaGetSymbolAddress(&wps, d_wpTs);

    k_init<<<1, 512>>>();
    k_prep<<<48, 256>>>(c1w, pww);
    cudaMemcpyToSymbolAsync(cW1T, w1s, 64 * 64 * 4, 0,
                            cudaMemcpyDeviceToDevice, 0);
    cudaMemcpyToSymbolAsync(cWpT, wps, 192 * 64 * 4, 0,
                            cudaMemcpyDeviceToDevice, 0);
    k_conv1<<<2048, 256, C1_BYTES>>>(x, c1b);
    // launch #4 -> profiled next round
    k_rest<<<dim3(16, 16, 8), NT, R_BYTES>>>(
        x, d1w, d1b, d2w, d2b, d3w, d3b, pwb);
    k_ca<<<8, 64>>>(caw1, caw2);
    k_sp<<<BB * HH, 256>>>();
    k_sa<<<dim3(16, 16, 8), dim3(16, 16)>>>(saw, sab);
    k_gnstats<<<dim3(16, 64, 8), 256>>>();
    k_fin<<<dim3(16, 64, 8), 256>>>((float *)d_out, gng, gnb);
}

// round 17
// speedup vs baseline: 2.0728x; 1.1799x over previous
#include <cuda_runtime.h>
#include <cuda_bf16.h>
#include <cstdint>

// Problem constants
#define BB 8
#define CC 64
#define HH 256
#define WW 256
#define HW 65536
#define TILE 16
#define HALO 2
#define EXT 20
#define EXT2 400
#define NT 256

typedef unsigned long long ull;

// ---------------- weights in constant memory (64KB exactly) ------------------
__constant__ float cW1T[64 * 64];      // conv1 [ci][co]
__constant__ float cWpT[192 * 64];     // pw    [c3][o]

// ---------------- scratch ----------------------------------------------------
__device__ float d_w1Ts[64 * 64];      // transpose staging
__device__ float d_wpTs[192 * 64];
__device__ float d_h[BB * CC * HW];
__device__ float d_y[BB * CC * HW];
__device__ float d_ca[BB * CC];
__device__ float d_spmean[BB * HW];
__device__ float d_spmax[BB * HW];
__device__ float d_sa[BB * HW];
__device__ float d_gsum[BB * CC];
__device__ unsigned int d_gmax[BB * CC];
__device__ float d_gnsum[BB * 8];
__device__ float d_gnsq[BB * 8];

// ---------------- helpers ---------------------------------------------------
__device__ __forceinline__ float silu_f(float v) {
    return __fdividef(v, 1.f + __expf(-v));
}
__device__ __forceinline__ unsigned fenc(float f) {
    unsigned u = __float_as_uint(f);
    return (u & 0x80000000u) ? ~u : (u | 0x80000000u);
}
__device__ __forceinline__ float fdec(unsigned u) {
    return (u & 0x80000000u) ? __uint_as_float(u ^ 0x80000000u)
                             : __uint_as_float(~u);
}
__device__ __forceinline__ void fma2(ull &d, ull a, ull b) {
    asm("fma.rn.f32x2 %0, %1, %2, %0;" : "+l"(d) : "l"(a), "l"(b));
}
__device__ __forceinline__ ull splat2(float v) {
    unsigned u = __float_as_uint(v);
    ull r;
    asm("mov.b64 %0, {%1, %2};" : "=l"(r) : "r"(u), "r"(u));
    return r;
}
__device__ __forceinline__ void unpack2(ull v, float &lo, float &hi) {
    unsigned a, b;
    asm("mov.b64 {%0, %1}, %2;" : "=r"(a), "=r"(b) : "l"(v));
    lo = __uint_as_float(a);
    hi = __uint_as_float(b);
}

// 32 packed FMAs: 4 pixels (xv) x 16 co, weights from __constant__
__device__ __forceinline__ void gemm32c(ull *acc, float4 xv, const float *wbase) {
    ulonglong2 W0 = *(const ulonglong2 *)(wbase);
    ulonglong2 W1 = *(const ulonglong2 *)(wbase + 4);
    ulonglong2 W2 = *(const ulonglong2 *)(wbase + 8);
    ulonglong2 W3 = *(const ulonglong2 *)(wbase + 12);
    ull s;
    s = splat2(xv.x);
    fma2(acc[0], W0.x, s); fma2(acc[1], W0.y, s);
    fma2(acc[2], W1.x, s); fma2(acc[3], W1.y, s);
    fma2(acc[4], W2.x, s); fma2(acc[5], W2.y, s);
    fma2(acc[6], W3.x, s); fma2(acc[7], W3.y, s);
    s = splat2(xv.y);
    fma2(acc[8],  W0.x, s); fma2(acc[9],  W0.y, s);
    fma2(acc[10], W1.x, s); fma2(acc[11], W1.y, s);
    fma2(acc[12], W2.x, s); fma2(acc[13], W2.y, s);
    fma2(acc[14], W3.x, s); fma2(acc[15], W3.y, s);
    s = splat2(xv.z);
    fma2(acc[16], W0.x, s); fma2(acc[17], W0.y, s);
    fma2(acc[18], W1.x, s); fma2(acc[19], W1.y, s);
    fma2(acc[20], W2.x, s); fma2(acc[21], W2.y, s);
    fma2(acc[22], W3.x, s); fma2(acc[23], W3.y, s);
    s = splat2(xv.w);
    fma2(acc[24], W0.x, s); fma2(acc[25], W0.y, s);
    fma2(acc[26], W1.x, s); fma2(acc[27], W1.y, s);
    fma2(acc[28], W2.x, s); fma2(acc[29], W2.y, s);
    fma2(acc[30], W3.x, s); fma2(acc[31], W3.y, s);
}

// ---------------- kernel 0: init + weight transpose ------------------------
__global__ void k_init() {
    int t = threadIdx.x;
    if (t < BB * CC) { d_gsum[t] = 0.f; d_gmax[t] = 0u; }
    if (t < BB * 8)  { d_gnsum[t] = 0.f; d_gnsq[t] = 0.f; }
}
__global__ void k_prep(const float *__restrict__ c1w, const float *__restrict__ pww) {
    int t = blockIdx.x * 256 + threadIdx.x;
    if (t < 4096) {
        int ci = t >> 6, co = t & 63;
        d_w1Ts[t] = c1w[(co << 6) | ci];
    }
    if (t < 12288) {
        int c3 = t >> 6, o = t & 63;
        d_wpTs[t] = pww[o * 192 + c3];
    }
}

// ---------------- kernel A: conv1 GEMM, h = silu(W1 x + b1) ----------------
#define C1_SX   0
#define C1_B    16384
#define C1_FLOATS 16448
#define C1_BYTES (C1_FLOATS * 4)

__global__ void __launch_bounds__(256, 2)
k_conv1(const float *__restrict__ x, const float *__restrict__ c1b) {
    extern __shared__ float smem[];
    float *sX   = smem + C1_SX;
    float *sCb1 = smem + C1_B;

    const int tid = threadIdx.x;
    const int b = blockIdx.x >> 8;
    const int pbase = (blockIdx.x & 255) << 8;
    const float *xb = x + ((b << 6) << 16) + pbase;

    if (tid < 64) sCb1[tid] = c1b[tid];
#pragma unroll
    for (int k = 0; k < 64; k += 4) {
        int i = (k << 8) + tid;
        sX[i]       = xb[((k + 0) << 16) + tid];
        sX[i + 256] = xb[((k + 1) << 16) + tid];
        sX[i + 512] = xb[((k + 2) << 16) + tid];
        sX[i + 768] = xb[((k + 3) << 16) + tid];
    }
    __syncthreads();

    const int wid = tid >> 5, lane = tid & 31;
    const int cog = wid & 3;                     // warp-uniform
    const int quad = ((wid >> 2) << 5) + lane;   // 0..63
    const int col0 = quad << 2;

    ull acc[32];
#pragma unroll
    for (int j = 0; j < 32; j++) acc[j] = 0ull;

#pragma unroll 4
    for (int ci = 0; ci < 64; ci++) {
        float4 xv = *(const float4 *)(sX + (ci << 8) + col0);
        gemm32c(acc, xv, cW1T + (ci << 6) + (cog << 4));
    }

    float *hb = d_h + ((b << 6) << 16) + pbase;
#pragma unroll
    for (int kp = 0; kp < 8; kp++) {
        int co = (cog << 4) + 2 * kp;
        float b0 = sCb1[co], b1 = sCb1[co + 1];
        float4 v0, v1;
        float lo, hi;
        unpack2(acc[0 * 8 + kp], lo, hi);
        v0.x = silu_f(lo + b0); v1.x = silu_f(hi + b1);
        unpack2(acc[1 * 8 + kp], lo, hi);
        v0.y = silu_f(lo + b0); v1.y = silu_f(hi + b1);
        unpack2(acc[2 * 8 + kp], lo, hi);
        v0.z = silu_f(lo + b0); v1.z = silu_f(hi + b1);
        unpack2(acc[3 * 8 + kp], lo, hi);
        v0.w = silu_f(lo + b0); v1.w = silu_f(hi + b1);
        *(float4 *)(hb + (co << 16) + col0)       = v0;
        *(float4 *)(hb + ((co + 1) << 16) + col0) = v1;
    }
}

// ---------------- kernel B: dw(1/3/5) + pw GEMM + residual + reductions ----
// sHci: h chunk ext tile [8 ch][20 rows][stride 48] -> conflict-free LDS.128
// windows (bank-group perm per phase); only cols 0..19 populated/read.
#define SHCI_RS 48
#define SHCI_CS (20 * SHCI_RS)           // 960
#define R_HCI 0                          // 8*960 = 7680
#define R_HC  7680                       // h123 chunk [24][256]  6144
#define R_DW2 13824                      // 576
#define R_DW3 14400                      // 1600
#define R_DW1 16000
#define R_BD1 16064
#define R_BD2 16128
#define R_BD3 16192
#define R_BPW 16256
#define R_SUM 16320                      // [8][16]
#define R_MAX 16448                      // [8][16]
#define R_FLOATS 16576
#define R_BYTES (R_FLOATS * 4)

__global__ void __launch_bounds__(NT, 2)
k_rest(const float *__restrict__ x,
       const float *__restrict__ d1w, const float *__restrict__ d1b,
       const float *__restrict__ d2w, const float *__restrict__ d2b,
       const float *__restrict__ d3w, const float *__restrict__ d3b,
       const float *__restrict__ pwb) {
    extern __shared__ float smem[];
    float *sHci = smem + R_HCI;
    float *sHC  = smem + R_HC;
    float *sDw2 = smem + R_DW2;
    float *sDw3 = smem + R_DW3;
    float *sDw1 = smem + R_DW1;
    float *sBd1 = smem + R_BD1;
    float *sBd2 = smem + R_BD2;
    float *sBd3 = smem + R_BD3;
    float *sBpw = smem + R_BPW;
    float *sSum = smem + R_SUM;
    float *sMax = smem + R_MAX;

    const int tid = threadIdx.x;
    const int tileX = blockIdx.x, tileY = blockIdx.y, b = blockIdx.z;
    const int x0 = tileX * TILE - HALO, y0 = tileY * TILE - HALO;
    const float *hbase = d_h + ((b << 6) << 16);

    for (int i = tid; i < 576;  i += NT) sDw2[i] = d2w[i];
    for (int i = tid; i < 1600; i += NT) sDw3[i] = d3w[i];
    if (tid < 64) {
        sDw1[tid] = d1w[tid];
        sBd1[tid] = d1b[tid]; sBd2[tid] = d2b[tid];
        sBd3[tid] = d3b[tid]; sBpw[tid] = pwb[tid];
    }
    __syncthreads();

    const int wid = tid >> 5, lane = tid & 31;
    const int cog = wid & 3;                     // warp-uniform
    const int quad = ((wid >> 2) << 5) + lane;   // 0..63
    const int col0 = quad << 2;
    // dw mapping: thread owns quad q (4 px) x 2 channels
    const int q = tid & 63, cp = tid >> 6;
    const int qy = q >> 2, qx = (q & 3) << 2;

    ull acc[32];
#pragma unroll
    for (int j = 0; j < 32; j++) acc[j] = 0ull;

#pragma unroll 1
    for (int cc = 0; cc < 8; cc++) {
        const int c0 = cc << 3;
        // load h chunk ext tile (8 ch x 20x20) into strided sHci
        for (int i = tid; i < 8 * EXT2; i += NT) {
            int ii = i / EXT2;
            int p = i - ii * EXT2;
            int py = p / EXT, px = p - py * EXT;
            int gy = y0 + py, gx = x0 + px;
            float v = 0.f;
            if ((unsigned)gy < HH && (unsigned)gx < WW)
                v = hbase[((c0 + ii) << 16) + (gy << 8) + gx];
            sHci[ii * SHCI_CS + py * SHCI_RS + px] = v;
        }
        __syncthreads();

        // dw-pass: vectorized 4-pixel windows, 10 LDS.128 per channel
#pragma unroll
        for (int ic = 0; ic < 2; ic++) {
            const int lc = (cp << 1) + ic;       // local channel 0..7
            const int c = c0 + lc;
            const float *wb = sHci + lc * SHCI_CS + qy * SHCI_RS + qx;
            const float *wp3 = sDw3 + c * 25;
            const float *wp2 = sDw2 + c * 9;
            float bd3 = sBd3[c], bd2 = sBd2[c];
            float h3v0 = bd3, h3v1 = bd3, h3v2 = bd3, h3v3 = bd3;
            float h2v0 = bd2, h2v1 = bd2, h2v2 = bd2, h2v3 = bd2;
            float h1v0, h1v1, h1v2, h1v3;
#pragma unroll
            for (int r = 0; r < 5; r++) {
                float4 A = *(const float4 *)(wb + r * SHCI_RS);
                float4 B = *(const float4 *)(wb + r * SHCI_RS + 4);
                float w0 = A.x, w1 = A.y, w2 = A.z, w3 = A.w;
                float w4 = B.x, w5 = B.y, w6 = B.z, w7 = B.w;
                float wv[8] = {w0, w1, w2, w3, w4, w5, w6, w7};
#pragma unroll
                for (int k = 0; k < 5; k++) {
                    float c5 = wp3[r * 5 + k];
                    h3v0 = fmaf(c5, wv[k],     h3v0);
                    h3v1 = fmaf(c5, wv[k + 1], h3v1);
                    h3v2 = fmaf(c5, wv[k + 2], h3v2);
                    h3v3 = fmaf(c5, wv[k + 3], h3v3);
                }
                if (r >= 1 && r <= 3) {
#pragma unroll
                    for (int k = 0; k < 3; k++) {
                        float c3 = wp2[(r - 1) * 3 + k];
                        h2v0 = fmaf(c3, wv[k + 1], h2v0);
                        h2v1 = fmaf(c3, wv[k + 2], h2v1);
                        h2v2 = fmaf(c3, wv[k + 3], h2v2);
                        h2v3 = fmaf(c3, wv[k + 4], h2v3);
                    }
                }
                if (r == 2) {
                    float c1 = sDw1[c], bd1 = sBd1[c];
                    h1v0 = fmaf(c1, wv[2], bd1);
                    h1v1 = fmaf(c1, wv[3], bd1);
                    h1v2 = fmaf(c1, wv[4], bd1);
                    h1v3 = fmaf(c1, wv[5], bd1);
                }
            }
            *(float4 *)(sHC + (0 * 8 + lc) * 256 + (q << 2)) =
                make_float4(h1v0, h1v1, h1v2, h1v3);
            *(float4 *)(sHC + (1 * 8 + lc) * 256 + (q << 2)) =
                make_float4(h2v0, h2v1, h2v2, h2v3);
            *(float4 *)(sHC + (2 * 8 + lc) * 256 + (q << 2)) =
                make_float4(h3v0, h3v1, h3v2, h3v3);
        }
        __syncthreads();

        // GEMM accumulate over the 24 k-rows of this chunk
#pragma unroll
        for (int t = 0; t < 3; t++)
#pragma unroll
            for (int i = 0; i < 8; i++) {
                const int krow = t * 64 + c0 + i;
                float4 hv = *(const float4 *)(sHC + (t * 8 + i) * 256 + col0);
                gemm32c(acc, hv, cWpT + (krow << 6) + (cog << 4));
            }
        __syncthreads();
    }

    // epilogue: silu(pw+bias) + residual + silu -> d_y, then warp reductions
    const int prow = col0 >> 4, pcol = col0 & 15;
    const int gpix0 = ((tileY * TILE + prow) << 8) + tileX * TILE + pcol;
    const float *xq = x + ((b << 6) << 16) + gpix0;
    float *yq = d_y + ((b << 6) << 16) + gpix0;

#pragma unroll
    for (int kp = 0; kp < 8; kp++) {
        int co0 = (cog << 4) + 2 * kp, co1 = co0 + 1;
        float bp0 = sBpw[co0], bp1 = sBpw[co1];
        float4 xv0 = *(const float4 *)(xq + (co0 << 16));
        float4 xv1 = *(const float4 *)(xq + (co1 << 16));
        float4 y0, y1;
        float lo, hi;
        unpack2(acc[0 * 8 + kp], lo, hi);
        y0.x = silu_f(silu_f(lo + bp0) + xv0.x);
        y1.x = silu_f(silu_f(hi + bp1) + xv1.x);
        unpack2(acc[1 * 8 + kp], lo, hi);
        y0.y = silu_f(silu_f(lo + bp0) + xv0.y);
        y1.y = silu_f(silu_f(hi + bp1) + xv1.y);
        unpack2(acc[2 * 8 + kp], lo, hi);
        y0.z = silu_f(silu_f(lo + bp0) + xv0.z);
        y1.z = silu_f(silu_f(hi + bp1) + xv1.z);
        unpack2(acc[3 * 8 + kp], lo, hi);
        y0.w = silu_f(silu_f(lo + bp0) + xv0.w);
        y1.w = silu_f(silu_f(hi + bp1) + xv1.w);
        *(float4 *)(yq + (co0 << 16)) = y0;
        *(float4 *)(yq + (co1 << 16)) = y1;

        float s0 = (y0.x + y0.y) + (y0.z + y0.w);
        float s1 = (y1.x + y1.y) + (y1.z + y1.w);
        float m0 = fmaxf(fmaxf(y0.x, y0.y), fmaxf(y0.z, y0.w));
        float m1 = fmaxf(fmaxf(y1.x, y1.y), fmaxf(y1.z, y1.w));
#pragma unroll
        for (int o = 16; o; o >>= 1) {
            s0 += __shfl_xor_sync(0xFFFFFFFFu, s0, o);
            s1 += __shfl_xor_sync(0xFFFFFFFFu, s1, o);
            m0 = fmaxf(m0, __shfl_xor_sync(0xFFFFFFFFu, m0, o));
            m1 = fmaxf(m1, __shfl_xor_sync(0xFFFFFFFFu, m1, o));
        }
        if (lane == 0) {
            sSum[wid * 16 + 2 * kp]     = s0;
            sSum[wid * 16 + 2 * kp + 1] = s1;
            sMax[wid * 16 + 2 * kp]     = m0;
            sMax[wid * 16 + 2 * kp + 1] = m1;
        }
    }
    __syncthreads();

    if (tid < 64) {
        int cg = tid >> 4, k = tid & 15;
        float s = sSum[cg * 16 + k] + sSum[(cg + 4) * 16 + k];
        float m = fmaxf(sMax[cg * 16 + k], sMax[(cg + 4) * 16 + k]);
        atomicAdd(&d_gsum[(b << 6) | tid], s);
        atomicMax(&d_gmax[(b << 6) | tid], fenc(m));
    }
}

// ---------------- kernel 2: channel attention MLP --------------------------
__global__ void k_ca(const float *__restrict__ caw1, const float *__restrict__ caw2) {
    int b = blockIdx.x, c = threadIdx.x;
    __shared__ float pa[64], pm[64], ha[8], hm[8];
    pa[c] = d_gsum[(b << 6) | c] * (1.f / 65536.f);
    pm[c] = fdec(d_gmax[(b << 6) | c]);
    __syncthreads();
    if (c < 8) {
        float sa_ = 0.f, sm_ = 0.f;
#pragma unroll
        for (int i = 0; i < 64; i++) {
            float w = caw1[c * 64 + i];
            sa_ += w * pa[i];
            sm_ += w * pm[i];
        }
        ha[c] = fmaxf(sa_, 0.f);
        hm[c] = fmaxf(sm_, 0.f);
    }
    __syncthreads();
    float oa = 0.f, om = 0.f;
#pragma unroll
    for (int j = 0; j < 8; j++) {
        float w = caw2[c * 8 + j];
        oa += w * ha[j];
        om += w * hm[j];
    }
    d_ca[(b << 6) | c] = silu_f(oa + om);
}

// ---------------- kernel 3: spatial mean/max over channels -----------------
__global__ void k_sp() {
    int b = blockIdx.x >> 8;
    int y = blockIdx.x & 255;
    int xx = threadIdx.x;
    int p = (y << 8) | xx;
    const float *yb = d_y + ((b << 6) << 16) + p;
    const float *cab = d_ca + (b << 6);
    float s = 0.f, m = -3e38f;
#pragma unroll 8
    for (int c = 0; c < 64; c++) {
        float v = cab[c] * yb[c << 16];
        s += v;
        m = fmaxf(m, v);
    }
    d_spmean[(b << 16) | p] = s * (1.f / 64.f);
    d_spmax[(b << 16) | p] = m;
}

// ---------------- kernel 4: spatial attention 7x7 conv ---------------------
__global__ void k_sa(const float *__restrict__ saw, const float *__restrict__ sab) {
    __shared__ float sm[2][22][22];
    __shared__ float sw[98];
    int tx = threadIdx.x, ty = threadIdx.y;
    int tid = ty * 16 + tx;
    int b = blockIdx.z;
    int gx0 = blockIdx.x * 16 - 3, gy0 = blockIdx.y * 16 - 3;
    if (tid < 98) sw[tid] = saw[tid];
    for (int i = tid; i < 2 * 22 * 22; i += 256) {
        int ch = i / 484;
        int r = i - ch * 484;
        int py = r / 22, px = r - py * 22;
        int gy = gy0 + py, gx = gx0 + px;
        float v = 0.f;
        if ((unsigned)gy < HH && (unsigned)gx < WW)
            v = (ch ? d_spmax : d_spmean)[(b << 16) + (gy << 8) + gx];
        sm[ch][py][px] = v;
    }
    __syncthreads();
    float acc = sab[0];
#pragma unroll
    for (int ch = 0; ch < 2; ch++)
#pragma unroll
        for (int dy = 0; dy < 7; dy++)
#pragma unroll
            for (int dx = 0; dx < 7; dx++)
                acc = fmaf(sw[ch * 49 + dy * 7 + dx], sm[ch][ty + dy][tx + dx], acc);
    int gy = blockIdx.y * 16 + ty, gx = blockIdx.x * 16 + tx;
    d_sa[(b << 16) + (gy << 8) + gx] = silu_f(acc);
}

// ---------------- kernel 5: groupnorm statistics ---------------------------
__global__ void k_gnstats() {
    int chunk = blockIdx.x, c = blockIdx.y, b = blockIdx.z;
    int tid = threadIdx.x;
    float cav = d_ca[(b << 6) | c];
    const float *yb = d_y + (((b << 6) | c) << 16);
    const float *sab = d_sa + (b << 16);
    int base = chunk * 4096;
    float s = 0.f, sq = 0.f;
#pragma unroll
    for (int i = 0; i < 16; i++) {
        int p = base + (i << 8) + tid;
        float v = sab[p] * cav * yb[p];
        s += v;
        sq += v * v;
    }
#pragma unroll
    for (int o = 16; o; o >>= 1) {
        s  += __shfl_xor_sync(0xFFFFFFFFu, s, o);
        sq += __shfl_xor_sync(0xFFFFFFFFu, sq, o);
    }
    __shared__ float ws[8], wq[8];
    int w = tid >> 5, l = tid & 31;
    if (!l) { ws[w] = s; wq[w] = sq; }
    __syncthreads();
    if (tid == 0) {
        float S = 0.f, Q = 0.f;
#pragma unroll
        for (int i = 0; i < 8; i++) { S += ws[i]; Q += wq[i]; }
        atomicAdd(&d_gnsum[(b << 3) | (c >> 3)], S);
        atomicAdd(&d_gnsq[(b << 3) | (c >> 3)], Q);
    }
}

// ---------------- kernel 6: groupnorm apply + silu -> out ------------------
__global__ void k_fin(float *__restrict__ out,
                      const float *__restrict__ gng, const float *__restrict__ gnb) {
    int chunk = blockIdx.x, c = blockIdx.y, b = blockIdx.z;
    int tid = threadIdx.x;
    float cav = d_ca[(b << 6) | c];
    int gi = (b << 3) | (c >> 3);
    const float Ninv = 1.f / 524288.f;
    float mu = d_gnsum[gi] * Ninv;
    float var = d_gnsq[gi] * Ninv - mu * mu;
    float inv = rsqrtf(var + 1e-5f);
    float ga = gng[c], be = gnb[c];
    int coff = ((b << 6) | c) << 16;
    const float *yb = d_y + coff;
    const float *sab = d_sa + (b << 16);
    float *ob = out + coff;
    int base = chunk * 4096;
#pragma unroll
    for (int i = 0; i < 16; i++) {
        int p = base + (i << 8) + tid;
        float v = sab[p] * cav * yb[p];
        float g = (v - mu) * inv * ga + be;
        ob[p] = silu_f(g);
    }
}

// ---------------- launch ----------------------------------------------------
extern "C" void kernel_launch(void *const *d_in, const int *in_sizes, int n_in,
                              void *d_out, int out_size) {
    const float *x      = (const float *)d_in[0];
    const float *c1w    = (const float *)d_in[1];
    const float *c1b    = (const float *)d_in[2];
    const float *d1w    = (const float *)d_in[3];
    const float *d1b    = (const float *)d_in[4];
    const float *d2w    = (const float *)d_in[5];
    const float *d2b    = (const float *)d_in[6];
    const float *d3w    = (const float *)d_in[7];
    const float *d3b    = (const float *)d_in[8];
    const float *pww    = (const float *)d_in[9];
    const float *pwb    = (const float *)d_in[10];
    const float *caw1   = (const float *)d_in[11];
    const float *caw2   = (const float *)d_in[12];
    const float *saw    = (const float *)d_in[13];
    const float *sab    = (const float *)d_in[14];
    const float *gng    = (const float *)d_in[15];
    const float *gnb    = (const float *)d_in[16];

    cudaFuncSetAttribute(k_conv1, cudaFuncAttributeMaxDynamicSharedMemorySize,
                         C1_BYTES);
    cudaFuncSetAttribute(k_rest, cudaFuncAttributeMaxDynamicSharedMemorySize,
                         R_BYTES);

    void *w1s = nullptr, *wps = nullptr;
    cudaGetSymbolAddress(&w1s, d_w1Ts);
    cudaGetSymbolAddress(&wps, d_wpTs);

    k_init<<<1, 512>>>();
    k_prep<<<48, 256>>>(c1w, pww);
    cudaMemcpyToSymbolAsync(cW1T, w1s, 64 * 64 * 4, 0,
                            cudaMemcpyDeviceToDevice, 0);
    cudaMemcpyToSymbolAsync(cWpT, wps, 192 * 64 * 4, 0,
                            cudaMemcpyDeviceToDevice, 0);
    k_conv1<<<2048, 256, C1_BYTES>>>(x, c1b);
    // launch #4 -> profiled next round
    k_rest<<<dim3(16, 16, 8), NT, R_BYTES>>>(
        x, d1w, d1b, d2w, d2b, d3w, d3b, pwb);
    k_ca<<<8, 64>>>(caw1, caw2);
    k_sp<<<BB * HH, 256>>>();
    k_sa<<<dim3(16, 16, 8), dim3(16, 16)>>>(saw, sab);
    k_gnstats<<<dim3(16, 64, 8), 256>>>();
    k_fin<<<dim3(16, 64, 8), 256>>>((float *)d_out, gng, gnb);
}